// round 1
// baseline (speedup 1.0000x reference)
#include <cuda_runtime.h>

#define BB    16
#define CC    112
#define HH    64
#define HWN   4096
#define NHEAD 4
#define HD    28
#define NWIN  256
#define TOPK  128
#define SCALE 0.18898223650461363f   // 28^-0.5

// ---------------- scratch (device globals; no allocation allowed) ------------
__device__ __align__(16) float g_q[BB * HWN * CC];
__device__ __align__(16) float g_k[BB * HWN * CC];
__device__ __align__(16) float g_v[BB * HWN * CC];
__device__ __align__(16) float g_o[BB * HWN * CC];

// =============================================================================
// Kernel A: QKV projection.
//   qkv[b, hw, d] = sum_c x[b, c, hw] * Wqkv[d, c];  q scaled by SCALE.
// Block: (batch b, tile of 128 pixels). smem: xs[112][128], ws[112][112] (one
// segment of Wqkv at a time), stage[128][112] for coalesced output.
// =============================================================================
__global__ __launch_bounds__(256) void qkv_kernel(const float* __restrict__ x,
                                                  const float* __restrict__ Wqkv) {
    extern __shared__ float sm[];
    float* xs = sm;                  // [c][128]        14336 floats
    float* ws = sm + 14336;          // [112][112]      12544 floats
    float* st = sm + 14336 + 12544;  // [128][112]      14336 floats

    const int tid = threadIdx.x;
    const int b   = blockIdx.y;
    const int hw0 = blockIdx.x * 128;

    // load x tile: x[b][c][hw0 .. hw0+128)
    for (int i = tid; i < 3584; i += 256) {
        int c = i >> 5, p4 = i & 31;
        ((float4*)xs)[c * 32 + p4] =
            ((const float4*)(x + (b * CC + c) * HWN + hw0))[p4];
    }

    for (int seg = 0; seg < 3; seg++) {
        __syncthreads();  // also guards stage reuse across segments
        // load Wqkv segment rows [seg*112, seg*112+112)
        const float4* wsrc = (const float4*)(Wqkv + seg * CC * CC);
        for (int i = tid; i < 3136; i += 256) ((float4*)ws)[i] = wsrc[i];
        __syncthreads();

        const float scl = (seg == 0) ? SCALE : 1.0f;
        #pragma unroll
        for (int k = 0; k < 2; k++) {
            int t  = tid + k * 256;
            int pg = t & 31;         // pixel group (4 px)
            int dg = t >> 5;         // d group (7 d), 0..15, uniform per warp
            int px = pg * 4;
            float acc[4][7];
            #pragma unroll
            for (int i = 0; i < 4; i++)
                #pragma unroll
                for (int j = 0; j < 7; j++) acc[i][j] = 0.0f;

            const float* wsp = ws + dg * 7 * CC;
            for (int c = 0; c < CC; c++) {
                float4 xv = *(const float4*)(xs + c * 128 + px);
                #pragma unroll
                for (int j = 0; j < 7; j++) {
                    float wv = wsp[j * CC + c];      // broadcast within warp
                    acc[0][j] += xv.x * wv;
                    acc[1][j] += xv.y * wv;
                    acc[2][j] += xv.z * wv;
                    acc[3][j] += xv.w * wv;
                }
            }
            #pragma unroll
            for (int i = 0; i < 4; i++)
                #pragma unroll
                for (int j = 0; j < 7; j++)
                    st[(px + i) * CC + dg * 7 + j] = acc[i][j] * scl;
        }
        __syncthreads();

        float* dst = (seg == 0 ? g_q : (seg == 1 ? g_k : g_v)) + (b * HWN + hw0) * CC;
        for (int i = tid; i < 3584; i += 256)
            ((float4*)dst)[i] = ((const float4*)st)[i];
    }
}

// =============================================================================
// Kernel B: windowed top-k attention. One block per (batch, window).
// smem: Ks[128][112], Vs[128][112], Qs[16][112], S[4][16][128], poss[128]
// =============================================================================
__global__ __launch_bounds__(256) void attn_kernel(const int* __restrict__ topk) {
    extern __shared__ float sm[];
    float* Ks   = sm;                 // 14336
    float* Vs   = sm + 14336;         // 14336
    float* Qs   = sm + 28672;         // 1792
    float* S    = sm + 30464;         // 8192
    int*   poss = (int*)(sm + 38656); // 128 ints

    const int tid = threadIdx.x;
    const int w   = blockIdx.x & (NWIN - 1);
    const int b   = blockIdx.x >> 8;
    const int wy  = w >> 4, wx = w & 15;

    if (tid < TOPK) poss[tid] = topk[w * TOPK + tid];
    __syncthreads();

    // gather K, V (128 rows x 112 floats, float4) — L2 resident
    for (int i = tid; i < 3584; i += 256) {
        int row = i / 28, c4 = i - row * 28;
        int base4 = (b * HWN + poss[row]) * 28 + c4;
        ((float4*)Ks)[i] = ((const float4*)g_k)[base4];
        ((float4*)Vs)[i] = ((const float4*)g_v)[base4];
    }
    // load Q (already scaled)
    for (int i = tid; i < 448; i += 256) {
        int qi = i / 28, c4 = i - qi * 28;
        int hw = (wy * 4 + (qi >> 2)) * HH + wx * 4 + (qi & 3);
        ((float4*)Qs)[i] = ((const float4*)g_q)[(b * HWN + hw) * 28 + c4];
    }
    __syncthreads();

    // ---- S = Q K^T : thread tile = (head, 4 qi, 8 kj) ----
    {
        int kg = tid & 15;           // kj group: 8 keys
        int qg = (tid >> 4) & 3;     // qi group: 4 queries
        int h  = tid >> 6;           // head
        float acc[4][8];
        #pragma unroll
        for (int i = 0; i < 4; i++)
            #pragma unroll
            for (int j = 0; j < 8; j++) acc[i][j] = 0.0f;

        const float* qp = Qs + (qg * 4) * CC + h * HD;
        const float* kp = Ks + (kg * 8) * CC + h * HD;
        #pragma unroll
        for (int s = 0; s < 7; s++) {
            float4 kv[8];
            #pragma unroll
            for (int j = 0; j < 8; j++)
                kv[j] = *(const float4*)(kp + j * CC + s * 4);
            #pragma unroll
            for (int i = 0; i < 4; i++) {
                float4 qv = *(const float4*)(qp + i * CC + s * 4);
                #pragma unroll
                for (int j = 0; j < 8; j++)
                    acc[i][j] += qv.x * kv[j].x + qv.y * kv[j].y +
                                 qv.z * kv[j].z + qv.w * kv[j].w;
            }
        }
        float* srow = S + (h * 16 + qg * 4) * TOPK + kg * 8;
        #pragma unroll
        for (int i = 0; i < 4; i++)
            #pragma unroll
            for (int j = 0; j < 8; j++)
                srow[i * TOPK + j] = acc[i][j];
    }
    __syncthreads();

    // ---- softmax over kj: 4 threads (a quad within a warp) per row ----
    {
        int r   = tid >> 2;          // row 0..63 = h*16+qi
        int sub = tid & 3;
        float* row = S + r * TOPK + sub * 32;
        float mx = -1e30f;
        #pragma unroll 8
        for (int i = 0; i < 32; i++) mx = fmaxf(mx, row[i]);
        mx = fmaxf(mx, __shfl_xor_sync(0xffffffffu, mx, 1));
        mx = fmaxf(mx, __shfl_xor_sync(0xffffffffu, mx, 2));
        float sum = 0.0f;
        #pragma unroll 8
        for (int i = 0; i < 32; i++) {
            float e = __expf(row[i] - mx);
            row[i] = e;
            sum += e;
        }
        sum += __shfl_xor_sync(0xffffffffu, sum, 1);
        sum += __shfl_xor_sync(0xffffffffu, sum, 2);
        float inv = 1.0f / sum;
        #pragma unroll 8
        for (int i = 0; i < 32; i++) row[i] *= inv;
    }
    __syncthreads();

    // ---- O = P V : thread tile = (head, qi, 7 d's) ----
    {
        int dgrp = tid & 3;          // 7 d's each (4*7 = 28)
        int hq   = tid >> 2;         // 0..63
        int h    = hq >> 4, qi = hq & 15;
        const float* prow = S + hq * TOPK;
        const float* vp   = Vs + h * HD + dgrp * 7;
        float acc[7] = {0, 0, 0, 0, 0, 0, 0};
        #pragma unroll 4
        for (int kj = 0; kj < TOPK; kj++) {
            float p = prow[kj];
            const float* v = vp + kj * CC;
            #pragma unroll
            for (int j = 0; j < 7; j++) acc[j] += p * v[j];
        }
        int hw = (wy * 4 + (qi >> 2)) * HH + wx * 4 + (qi & 3);
        float* op = g_o + (b * HWN + hw) * CC + h * HD + dgrp * 7;
        #pragma unroll
        for (int j = 0; j < 7; j++) op[j] = acc[j];
    }
}

// =============================================================================
// Kernel C: output projection.
//   out[b, d, hw] = sum_c o[b, hw, c] * Wproj[d, c] + bproj[d]
// =============================================================================
__global__ __launch_bounds__(256) void proj_kernel(const float* __restrict__ Wp,
                                                   const float* __restrict__ bias,
                                                   float* __restrict__ out) {
    extern __shared__ float sm[];
    float* os = sm;            // [128][112]  14336
    float* wp = sm + 14336;    // [112][112]  12544
    float* bs = sm + 26880;    // 112

    const int tid = threadIdx.x;
    const int b   = blockIdx.y;
    const int hw0 = blockIdx.x * 128;

    const float4* osrc = ((const float4*)g_o) + (b * HWN + hw0) * 28;
    for (int i = tid; i < 3584; i += 256) ((float4*)os)[i] = osrc[i];
    for (int i = tid; i < 3136; i += 256) ((float4*)wp)[i] = ((const float4*)Wp)[i];
    if (tid < CC) bs[tid] = bias[tid];
    __syncthreads();

    #pragma unroll
    for (int k = 0; k < 4; k++) {
        int t  = tid + k * 256;
        int pg = t & 63;       // 2 px each
        int dg = t >> 6;       // 0..15, uniform per warp
        int px = pg * 2;
        float acc[2][7];
        #pragma unroll
        for (int j = 0; j < 7; j++) {
            float bv = bs[dg * 7 + j];
            acc[0][j] = bv;
            acc[1][j] = bv;
        }
        const float* op0 = os + px * CC;
        const float* wr  = wp + dg * 7 * CC;
        for (int c4 = 0; c4 < 28; c4++) {
            float4 x0 = ((const float4*)op0)[c4];
            float4 x1 = ((const float4*)(op0 + CC))[c4];
            #pragma unroll
            for (int j = 0; j < 7; j++) {
                float4 wv = ((const float4*)(wr + j * CC))[c4];   // broadcast
                acc[0][j] += x0.x * wv.x + x0.y * wv.y + x0.z * wv.z + x0.w * wv.w;
                acc[1][j] += x1.x * wv.x + x1.y * wv.y + x1.z * wv.z + x1.w * wv.w;
            }
        }
        #pragma unroll
        for (int j = 0; j < 7; j++) {
            float2 v = make_float2(acc[0][j], acc[1][j]);
            *(float2*)(out + (b * CC + dg * 7 + j) * HWN + hw0 + px) = v;
        }
    }
}

// =============================================================================
extern "C" void kernel_launch(void* const* d_in, const int* in_sizes, int n_in,
                              void* d_out, int out_size) {
    const float* x     = (const float*)d_in[0];
    const float* Wqkv  = (const float*)d_in[1];
    const float* Wproj = (const float*)d_in[2];
    const float* bproj = (const float*)d_in[3];
    const int*   topk  = (const int*)d_in[4];
    float* out = (float*)d_out;

    const int smemA = (14336 + 12544 + 14336) * 4;          // 164864
    const int smemB = 38656 * 4 + 128 * 4;                  // 155136
    const int smemC = (14336 + 12544 + 112) * 4;            // 107968

    cudaFuncSetAttribute(qkv_kernel,  cudaFuncAttributeMaxDynamicSharedMemorySize, smemA);
    cudaFuncSetAttribute(attn_kernel, cudaFuncAttributeMaxDynamicSharedMemorySize, smemB);
    cudaFuncSetAttribute(proj_kernel, cudaFuncAttributeMaxDynamicSharedMemorySize, smemC);

    qkv_kernel<<<dim3(32, 16), 256, smemA>>>(x, Wqkv);
    attn_kernel<<<BB * NWIN, 256, smemB>>>(topk);
    proj_kernel<<<dim3(32, 16), 256, smemC>>>(Wproj, bproj, out);
}

// round 2
// speedup vs baseline: 1.8258x; 1.8258x over previous
#include <cuda_runtime.h>

#define BB    16
#define CC    112
#define HH    64
#define HWN   4096
#define NHEAD 4
#define HD    28
#define NWIN  256
#define TOPK  128
#define SCALE 0.18898223650461363f   // 28^-0.5

#define KV_STRIDE 116   // padded row stride (floats) for K/V/Q smem: 116%32=20 -> conflict-free
#define S_STRIDE  132   // padded row stride for S: 132%32=4 -> conflict-free P reads
#define ST_STRIDE 113   // qkv stage stride: 4*113%32=4 -> 4-way max on scalar stores

// ---------------- scratch (device globals; no allocation allowed) ------------
__device__ __align__(16) float g_q[BB * HWN * CC];
__device__ __align__(16) float g_k[BB * HWN * CC];
__device__ __align__(16) float g_v[BB * HWN * CC];
__device__ __align__(16) float g_o[BB * HWN * CC];

__device__ __forceinline__ float dot4(float4 a, float4 b) {
    return a.x * b.x + a.y * b.y + a.z * b.z + a.w * b.w;
}

// =============================================================================
// Kernel A: QKV projection. qkv[b,hw,d] = sum_c x[b,c,hw] * Wqkv[d,c]
// Block: (batch, 128-pixel tile), 512 threads.
// =============================================================================
__global__ __launch_bounds__(512) void qkv_kernel(const float* __restrict__ x,
                                                  const float* __restrict__ Wqkv) {
    extern __shared__ float sm[];
    float* xs = sm;                          // [c][128]      14336
    float* ws = sm + 14336;                  // [112][112]    12544
    float* st = sm + 14336 + 12544;          // [128][113]    14464

    const int tid = threadIdx.x;
    const int b   = blockIdx.y;
    const int hw0 = blockIdx.x * 128;

    // load x tile: x[b][c][hw0..hw0+128)
    for (int i = tid; i < 3584; i += 512) {
        int c = i >> 5, p4 = i & 31;
        ((float4*)xs)[c * 32 + p4] =
            ((const float4*)(x + (b * CC + c) * HWN + hw0))[p4];
    }

    const int pg = tid & 31;        // pixel group (4 px), lanes consecutive
    const int dg = tid >> 5;        // d group (7 d), uniform within warp
    const int px = pg * 4;

    for (int seg = 0; seg < 3; seg++) {
        __syncthreads();
        const float4* wsrc = (const float4*)(Wqkv + seg * CC * CC);
        for (int i = tid; i < 3136; i += 512) ((float4*)ws)[i] = wsrc[i];
        __syncthreads();

        const float scl = (seg == 0) ? SCALE : 1.0f;
        float acc[4][7];
        #pragma unroll
        for (int i = 0; i < 4; i++)
            #pragma unroll
            for (int j = 0; j < 7; j++) acc[i][j] = 0.0f;

        const float* wsp = ws + dg * 7 * CC;
        #pragma unroll 2
        for (int c4 = 0; c4 < 28; c4++) {
            float4 xv[4];
            #pragma unroll
            for (int u = 0; u < 4; u++)
                xv[u] = *(const float4*)(xs + (c4 * 4 + u) * 128 + px);
            #pragma unroll
            for (int j = 0; j < 7; j++) {
                float4 w4 = *(const float4*)(wsp + j * CC + c4 * 4);  // broadcast
                #pragma unroll
                for (int i = 0; i < 4; i++) {
                    acc[i][j] += ((const float*)&xv[0])[i] * w4.x
                               + ((const float*)&xv[1])[i] * w4.y
                               + ((const float*)&xv[2])[i] * w4.z
                               + ((const float*)&xv[3])[i] * w4.w;
                }
            }
        }
        #pragma unroll
        for (int i = 0; i < 4; i++)
            #pragma unroll
            for (int j = 0; j < 7; j++)
                st[(px + i) * ST_STRIDE + dg * 7 + j] = acc[i][j] * scl;
        __syncthreads();

        float* dst = (seg == 0 ? g_q : (seg == 1 ? g_k : g_v)) + (size_t)(b * HWN + hw0) * CC;
        for (int i = tid; i < 3584; i += 512) {
            int p = i / 28, c4 = i - p * 28;
            const float* s = st + p * ST_STRIDE + c4 * 4;
            float4 v = make_float4(s[0], s[1], s[2], s[3]);
            ((float4*)dst)[i] = v;
        }
    }
}

// =============================================================================
// Kernel B: windowed top-k attention. One block per (batch, window), 512 thr.
// =============================================================================
__global__ __launch_bounds__(512) void attn_kernel(const int* __restrict__ topk) {
    extern __shared__ float sm[];
    float* Ks   = sm;                        // 128 x 116 = 14848
    float* Vs   = sm + 14848;                // 128 x 116 = 14848
    float* Qs   = sm + 29696;                // 16 x 116  = 1856
    float* S    = sm + 31552;                // 64 x 132  = 8448
    int*   poss = (int*)(sm + 40000);        // 128

    const int tid = threadIdx.x;
    const int w   = blockIdx.x & (NWIN - 1);
    const int b   = blockIdx.x >> 8;
    const int wy  = w >> 4, wx = w & 15;

    if (tid < TOPK) poss[tid] = topk[w * TOPK + tid];
    __syncthreads();

    // gather K, V into padded rows
    for (int i = tid; i < 3584; i += 512) {
        int row = i / 28, c4 = i - row * 28;
        size_t base4 = (size_t)(b * HWN + poss[row]) * 28 + c4;
        ((float4*)Ks)[row * 29 + c4] = ((const float4*)g_k)[base4];
        ((float4*)Vs)[row * 29 + c4] = ((const float4*)g_v)[base4];
    }
    if (tid < 448) {
        int qi = tid / 28, c4 = tid - qi * 28;
        int hw = (wy * 4 + (qi >> 2)) * HH + wx * 4 + (qi & 3);
        ((float4*)Qs)[qi * 29 + c4] = ((const float4*)g_q)[(size_t)(b * HWN + hw) * 28 + c4];
    }
    __syncthreads();

    // ---- S = Q K^T : thread tile = 4 qi x 4 kj (kj = kg + 32j), per head ----
    {
        const int kg = tid & 31;            // lane = kg (consecutive rows)
        const int qg = (tid >> 5) & 3;
        const int h  = tid >> 7;
        float acc[4][4];
        #pragma unroll
        for (int i = 0; i < 4; i++)
            #pragma unroll
            for (int j = 0; j < 4; j++) acc[i][j] = 0.0f;

        const float* kp = Ks + kg * KV_STRIDE + h * HD;
        const float* qp = Qs + (qg * 4) * KV_STRIDE + h * HD;
        #pragma unroll
        for (int s = 0; s < 7; s++) {
            float4 kv[4], qv[4];
            #pragma unroll
            for (int j = 0; j < 4; j++)
                kv[j] = *(const float4*)(kp + j * 32 * KV_STRIDE + s * 4);
            #pragma unroll
            for (int i = 0; i < 4; i++)
                qv[i] = *(const float4*)(qp + i * KV_STRIDE + s * 4);
            #pragma unroll
            for (int i = 0; i < 4; i++)
                #pragma unroll
                for (int j = 0; j < 4; j++)
                    acc[i][j] += dot4(qv[i], kv[j]);
        }
        float* srow = S + (h * 16 + qg * 4) * S_STRIDE + kg;
        #pragma unroll
        for (int i = 0; i < 4; i++)
            #pragma unroll
            for (int j = 0; j < 4; j++)
                srow[i * S_STRIDE + j * 32] = acc[i][j];
    }
    __syncthreads();

    // ---- softmax: 8 threads per row, 16 elements each ----
    {
        int r   = tid >> 3;
        int sub = tid & 7;
        float* row = S + r * S_STRIDE + sub * 16;
        float mx = -1e30f;
        #pragma unroll
        for (int i = 0; i < 16; i++) mx = fmaxf(mx, row[i]);
        mx = fmaxf(mx, __shfl_xor_sync(0xffffffffu, mx, 1));
        mx = fmaxf(mx, __shfl_xor_sync(0xffffffffu, mx, 2));
        mx = fmaxf(mx, __shfl_xor_sync(0xffffffffu, mx, 4));
        float sum = 0.0f;
        #pragma unroll
        for (int i = 0; i < 16; i++) {
            float e = __expf(row[i] - mx);
            row[i] = e;
            sum += e;
        }
        sum += __shfl_xor_sync(0xffffffffu, sum, 1);
        sum += __shfl_xor_sync(0xffffffffu, sum, 2);
        sum += __shfl_xor_sync(0xffffffffu, sum, 4);
        float inv = 1.0f / sum;
        #pragma unroll
        for (int i = 0; i < 16; i++) row[i] *= inv;
    }
    __syncthreads();

    // ---- O = P V : thread = (row hq, 4 d's). slot 7 of each 8 idle ----
    {
        const int slot = tid & 7;
        const int hq   = tid >> 3;
        if (slot < 7) {
            const int h  = hq >> 4, qi = hq & 15;
            const float* prow = S + hq * S_STRIDE;
            const float* vp   = Vs + h * HD + slot * 4;
            float4 acc = make_float4(0.f, 0.f, 0.f, 0.f);
            #pragma unroll 4
            for (int kj = 0; kj < TOPK; kj++) {
                float p = prow[kj];
                float4 v = *(const float4*)(vp + kj * KV_STRIDE);
                acc.x += p * v.x; acc.y += p * v.y;
                acc.z += p * v.z; acc.w += p * v.w;
            }
            int hw = (wy * 4 + (qi >> 2)) * HH + wx * 4 + (qi & 3);
            ((float4*)g_o)[(size_t)(b * HWN + hw) * 28 + h * 7 + slot] = acc;
        }
    }
}

// =============================================================================
// Kernel C: output projection. out[b,d,hw] = sum_c o[b,hw,c]*Wproj[d,c] + b[d]
// Block: (batch, 128-pixel tile), 512 threads; thread = (px, 28 d's).
// =============================================================================
__global__ __launch_bounds__(512) void proj_kernel(const float* __restrict__ Wp,
                                                   const float* __restrict__ bias,
                                                   float* __restrict__ out) {
    extern __shared__ float sm[];
    float* os = sm;                  // [128][116]  14848
    float* wp = sm + 14848;          // [112][112]  12544
    float* bs = sm + 27392;          // 112

    const int tid = threadIdx.x;
    const int b   = blockIdx.y;
    const int hw0 = blockIdx.x * 128;

    const float4* osrc = ((const float4*)g_o) + (size_t)(b * HWN + hw0) * 28;
    for (int i = tid; i < 3584; i += 512) {
        int row = i / 28, c4 = i - row * 28;
        ((float4*)os)[row * 29 + c4] = osrc[i];
    }
    for (int i = tid; i < 3136; i += 512) ((float4*)wp)[i] = ((const float4*)Wp)[i];
    if (tid < CC) bs[tid] = bias[tid];
    __syncthreads();

    const int px = tid & 127;        // lanes = consecutive pixels
    const int dg = tid >> 7;         // 0..3, uniform within warp
    float acc[28];
    #pragma unroll
    for (int j = 0; j < 28; j++) acc[j] = bs[dg * 28 + j];

    const float* orow = os + px * KV_STRIDE;
    const float* wrow = wp + dg * 28 * CC;
    #pragma unroll 2
    for (int c4 = 0; c4 < 28; c4++) {
        float4 xv = *(const float4*)(orow + c4 * 4);
        #pragma unroll
        for (int j = 0; j < 28; j++) {
            float4 w4 = *(const float4*)(wrow + j * CC + c4 * 4);  // broadcast
            acc[j] += dot4(xv, w4);
        }
    }
    float* op = out + ((size_t)b * CC + dg * 28) * HWN + hw0 + px;
    #pragma unroll
    for (int j = 0; j < 28; j++) op[j * HWN] = acc[j];
}

// =============================================================================
extern "C" void kernel_launch(void* const* d_in, const int* in_sizes, int n_in,
                              void* d_out, int out_size) {
    const float* x     = (const float*)d_in[0];
    const float* Wqkv  = (const float*)d_in[1];
    const float* Wproj = (const float*)d_in[2];
    const float* bproj = (const float*)d_in[3];
    const int*   topk  = (const int*)d_in[4];
    float* out = (float*)d_out;

    const int smemA = (14336 + 12544 + 128 * ST_STRIDE) * 4;   // 165376
    const int smemB = 40000 * 4 + 128 * 4;                     // 160512
    const int smemC = (14848 + 12544 + 112) * 4;               // 110016

    cudaFuncSetAttribute(qkv_kernel,  cudaFuncAttributeMaxDynamicSharedMemorySize, smemA);
    cudaFuncSetAttribute(attn_kernel, cudaFuncAttributeMaxDynamicSharedMemorySize, smemB);
    cudaFuncSetAttribute(proj_kernel, cudaFuncAttributeMaxDynamicSharedMemorySize, smemC);

    qkv_kernel<<<dim3(32, 16), 512, smemA>>>(x, Wqkv);
    attn_kernel<<<BB * NWIN, 512, smemB>>>(topk);
    proj_kernel<<<dim3(32, 16), 512, smemC>>>(Wproj, bproj, out);
}

// round 3
// speedup vs baseline: 2.0497x; 1.1226x over previous
#include <cuda_runtime.h>

#define BB    16
#define CC    112
#define HH    64
#define HWN   4096
#define NHEAD 4
#define HD    28
#define NWIN  256
#define TOPK  128
#define SCALE 0.18898223650461363f   // 28^-0.5

#define KV_STRIDE 116   // K/V/Q row stride (floats): 116/4=29 odd -> LDS.128 conflict-free
#define S_STRIDE  131   // S row stride: ODD -> conflict-free scalar row-per-lane access
#define ST_STRIDE 113   // qkv stage stride
#define BUF_STRIDE 29   // O-phase reduction buffer stride (odd)

// ---------------- scratch (device globals; no allocation allowed) ------------
__device__ __align__(16) float g_q[BB * HWN * CC];
__device__ __align__(16) float g_k[BB * HWN * CC];
__device__ __align__(16) float g_v[BB * HWN * CC];
__device__ __align__(16) float g_o[BB * HWN * CC];

__device__ __forceinline__ float dot4(float4 a, float4 b) {
    return a.x * b.x + a.y * b.y + a.z * b.z + a.w * b.w;
}

// =============================================================================
// Kernel A: QKV projection. qkv[b,hw,d] = sum_c x[b,c,hw] * Wqkv[d,c]
// 512 threads, 86KB smem -> 2 blocks/SM. W via warp-uniform __ldg (L1/L2).
// =============================================================================
__global__ __launch_bounds__(512, 2) void qkv_kernel(const float* __restrict__ x,
                                                     const float* __restrict__ Wqkv) {
    extern __shared__ float sm[];
    float* xs = sm;                          // [112][128]    14336
    float* st = sm + 14336;                  // [64][113]      7232

    const int tid = threadIdx.x;
    const int b   = blockIdx.y;
    const int hw0 = blockIdx.x * 128;

    // load x tile: x[b][c][hw0..hw0+128)
    for (int i = tid; i < 3584; i += 512) {
        int c = i >> 5, p4 = i & 31;
        ((float4*)xs)[c * 32 + p4] =
            ((const float4*)(x + (b * CC + c) * HWN + hw0))[p4];
    }
    __syncthreads();

    const int pg = tid & 31;        // pixel group (4 px), lanes consecutive
    const int dg = tid >> 5;        // d group (7 d), uniform within warp
    const int px = pg * 4;

    for (int seg = 0; seg < 3; seg++) {
        const float scl = (seg == 0) ? SCALE : 1.0f;
        float acc[4][7];
        #pragma unroll
        for (int i = 0; i < 4; i++)
            #pragma unroll
            for (int j = 0; j < 7; j++) acc[i][j] = 0.0f;

        const float* wsp = Wqkv + (seg * CC + dg * 7) * CC;
        #pragma unroll 2
        for (int c4 = 0; c4 < 28; c4++) {
            float4 xv[4];
            #pragma unroll
            for (int u = 0; u < 4; u++)
                xv[u] = *(const float4*)(xs + (c4 * 4 + u) * 128 + px);
            #pragma unroll
            for (int j = 0; j < 7; j++) {
                float4 w4 = __ldg((const float4*)(wsp + j * CC + c4 * 4));  // uniform
                #pragma unroll
                for (int i = 0; i < 4; i++) {
                    acc[i][j] += ((const float*)&xv[0])[i] * w4.x
                               + ((const float*)&xv[1])[i] * w4.y
                               + ((const float*)&xv[2])[i] * w4.z
                               + ((const float*)&xv[3])[i] * w4.w;
                }
            }
        }

        float* dst = (seg == 0 ? g_q : (seg == 1 ? g_k : g_v)) + (size_t)(b * HWN + hw0) * CC;
        #pragma unroll
        for (int wv = 0; wv < 2; wv++) {
            if ((pg >> 4) == wv) {
                #pragma unroll
                for (int i = 0; i < 4; i++)
                    #pragma unroll
                    for (int j = 0; j < 7; j++)
                        st[(px - wv * 64 + i) * ST_STRIDE + dg * 7 + j] = acc[i][j] * scl;
            }
            __syncthreads();
            for (int i = tid; i < 1792; i += 512) {
                int p = i / 28, c4 = i - p * 28;
                const float* s = st + p * ST_STRIDE + c4 * 4;
                ((float4*)dst)[wv * 1792 + i] = make_float4(s[0], s[1], s[2], s[3]);
            }
            __syncthreads();
        }
    }
}

// =============================================================================
// Kernel B: windowed top-k attention. One block per (batch, window), 1024 thr.
// =============================================================================
__global__ __launch_bounds__(1024, 1) void attn_kernel(const int* __restrict__ topk) {
    extern __shared__ float sm[];
    float* Ks   = sm;                        // 128 x 116 = 14848
    float* Vs   = sm + 14848;                // 128 x 116 = 14848
    float* Qs   = sm + 29696;                // 16 x 116  = 1856 (reused as O buf 64x29)
    float* S    = sm + 31552;                // 64 x 131  = 8384
    int*   poss = (int*)(sm + 39936);        // 128

    const int tid = threadIdx.x;
    const int w   = blockIdx.x & (NWIN - 1);
    const int b   = blockIdx.x >> 8;
    const int wy  = w >> 4, wx = w & 15;

    if (tid < TOPK) poss[tid] = topk[w * TOPK + tid];
    __syncthreads();

    // gather K, V into padded rows
    for (int i = tid; i < 3584; i += 1024) {
        int row = i / 28, c4 = i - row * 28;
        size_t base4 = (size_t)(b * HWN + poss[row]) * 28 + c4;
        ((float4*)Ks)[row * 29 + c4] = ((const float4*)g_k)[base4];
        ((float4*)Vs)[row * 29 + c4] = ((const float4*)g_v)[base4];
    }
    if (tid < 448) {
        int qi = tid / 28, c4 = tid - qi * 28;
        int hw = (wy * 4 + (qi >> 2)) * HH + wx * 4 + (qi & 3);
        ((float4*)Qs)[qi * 29 + c4] = ((const float4*)g_q)[(size_t)(b * HWN + hw) * 28 + c4];
    }
    __syncthreads();

    // ---- S = Q K^T : thread tile = 2 qi x 4 kj (kj = kg + 32j), per head ----
    {
        const int kg = tid & 31;             // lane = kg (consecutive rows)
        const int qg = (tid >> 5) & 7;       // 2 queries each
        const int h  = tid >> 8;
        float acc[2][4];
        #pragma unroll
        for (int i = 0; i < 2; i++)
            #pragma unroll
            for (int j = 0; j < 4; j++) acc[i][j] = 0.0f;

        const float* kp = Ks + kg * KV_STRIDE + h * HD;
        const float* qp = Qs + (qg * 2) * KV_STRIDE + h * HD;
        #pragma unroll
        for (int s = 0; s < 7; s++) {
            float4 kv[4], qv[2];
            #pragma unroll
            for (int j = 0; j < 4; j++)
                kv[j] = *(const float4*)(kp + j * 32 * KV_STRIDE + s * 4);
            #pragma unroll
            for (int i = 0; i < 2; i++)
                qv[i] = *(const float4*)(qp + i * KV_STRIDE + s * 4);
            #pragma unroll
            for (int i = 0; i < 2; i++)
                #pragma unroll
                for (int j = 0; j < 4; j++)
                    acc[i][j] += dot4(qv[i], kv[j]);
        }
        float* srow = S + (h * 16 + qg * 2) * S_STRIDE + kg;
        #pragma unroll
        for (int i = 0; i < 2; i++)
            #pragma unroll
            for (int j = 0; j < 4; j++)
                srow[i * S_STRIDE + j * 32] = acc[i][j];
    }
    __syncthreads();

    // ---- softmax: 16 threads per row, 8 elements each ----
    {
        int r   = tid >> 4;
        int sub = tid & 15;
        float* row = S + r * S_STRIDE + sub * 8;
        float mx = -1e30f;
        #pragma unroll
        for (int i = 0; i < 8; i++) mx = fmaxf(mx, row[i]);
        mx = fmaxf(mx, __shfl_xor_sync(0xffffffffu, mx, 1));
        mx = fmaxf(mx, __shfl_xor_sync(0xffffffffu, mx, 2));
        mx = fmaxf(mx, __shfl_xor_sync(0xffffffffu, mx, 4));
        mx = fmaxf(mx, __shfl_xor_sync(0xffffffffu, mx, 8));
        float sum = 0.0f;
        #pragma unroll
        for (int i = 0; i < 8; i++) {
            float e = __expf(row[i] - mx);
            row[i] = e;
            sum += e;
        }
        sum += __shfl_xor_sync(0xffffffffu, sum, 1);
        sum += __shfl_xor_sync(0xffffffffu, sum, 2);
        sum += __shfl_xor_sync(0xffffffffu, sum, 4);
        sum += __shfl_xor_sync(0xffffffffu, sum, 8);
        float inv = 1.0f / sum;
        #pragma unroll
        for (int i = 0; i < 8; i++) row[i] *= inv;
    }
    __syncthreads();

    // ---- O = P V : split-K over kj halves, reduce via smem buffer ----
    {
        const int hq   = tid & 63;
        const int slot = (tid >> 6) & 7;     // 0..6 active (4 d's each)
        const int half = tid >> 9;           // kj half
        const int h    = hq >> 4, qi = hq & 15;
        float4 acc = make_float4(0.f, 0.f, 0.f, 0.f);
        if (slot < 7) {
            const float* prow = S + hq * S_STRIDE + half * 64;
            const float* vp   = Vs + (half * 64) * KV_STRIDE + h * HD + slot * 4;
            #pragma unroll 4
            for (int kj = 0; kj < 64; kj++) {
                float p = prow[kj];
                float4 v = *(const float4*)(vp + kj * KV_STRIDE);
                acc.x += p * v.x; acc.y += p * v.y;
                acc.z += p * v.z; acc.w += p * v.w;
            }
            if (half == 1) {
                float* bp = Qs + hq * BUF_STRIDE + slot * 4;   // reuse Qs
                bp[0] = acc.x; bp[1] = acc.y; bp[2] = acc.z; bp[3] = acc.w;
            }
        }
        __syncthreads();
        if (slot < 7 && half == 0) {
            const float* bp = Qs + hq * BUF_STRIDE + slot * 4;
            acc.x += bp[0]; acc.y += bp[1]; acc.z += bp[2]; acc.w += bp[3];
            int hw = (wy * 4 + (qi >> 2)) * HH + wx * 4 + (qi & 3);
            ((float4*)g_o)[(size_t)(b * HWN + hw) * 28 + h * 7 + slot] = acc;
        }
    }
}

// =============================================================================
// Kernel C: output projection. out[b,d,hw] = sum_c o[b,hw,c]*Wproj[d,c] + b[d]
// =============================================================================
__global__ __launch_bounds__(512, 2) void proj_kernel(const float* __restrict__ Wp,
                                                      const float* __restrict__ bias,
                                                      float* __restrict__ out) {
    extern __shared__ float sm[];
    float* os = sm;                  // [128][116]  14848
    float* wp = sm + 14848;          // [112][112]  12544
    float* bs = sm + 27392;          // 112

    const int tid = threadIdx.x;
    const int b   = blockIdx.y;
    const int hw0 = blockIdx.x * 128;

    const float4* osrc = ((const float4*)g_o) + (size_t)(b * HWN + hw0) * 28;
    for (int i = tid; i < 3584; i += 512) {
        int row = i / 28, c4 = i - row * 28;
        ((float4*)os)[row * 29 + c4] = osrc[i];
    }
    for (int i = tid; i < 3136; i += 512) ((float4*)wp)[i] = ((const float4*)Wp)[i];
    if (tid < CC) bs[tid] = bias[tid];
    __syncthreads();

    const int px = tid & 127;        // lanes = consecutive pixels
    const int dg = tid >> 7;         // 0..3, uniform within warp
    float acc[28];
    #pragma unroll
    for (int j = 0; j < 28; j++) acc[j] = bs[dg * 28 + j];

    const float* orow = os + px * KV_STRIDE;
    const float* wrow = wp + dg * 28 * CC;
    #pragma unroll 2
    for (int c4 = 0; c4 < 28; c4++) {
        float4 xv = *(const float4*)(orow + c4 * 4);
        #pragma unroll
        for (int j = 0; j < 28; j++) {
            float4 w4 = *(const float4*)(wrow + j * CC + c4 * 4);  // broadcast
            acc[j] += dot4(xv, w4);
        }
    }
    float* op = out + ((size_t)b * CC + dg * 28) * HWN + hw0 + px;
    #pragma unroll
    for (int j = 0; j < 28; j++) op[j * HWN] = acc[j];
}

// =============================================================================
extern "C" void kernel_launch(void* const* d_in, const int* in_sizes, int n_in,
                              void* d_out, int out_size) {
    const float* x     = (const float*)d_in[0];
    const float* Wqkv  = (const float*)d_in[1];
    const float* Wproj = (const float*)d_in[2];
    const float* bproj = (const float*)d_in[3];
    const int*   topk  = (const int*)d_in[4];
    float* out = (float*)d_out;

    const int smemA = (14336 + 64 * ST_STRIDE) * 4;            // 86272
    const int smemB = 39936 * 4 + 128 * 4;                     // 160256
    const int smemC = (14848 + 12544 + 112) * 4;               // 110016

    cudaFuncSetAttribute(qkv_kernel,  cudaFuncAttributeMaxDynamicSharedMemorySize, smemA);
    cudaFuncSetAttribute(attn_kernel, cudaFuncAttributeMaxDynamicSharedMemorySize, smemB);
    cudaFuncSetAttribute(proj_kernel, cudaFuncAttributeMaxDynamicSharedMemorySize, smemC);

    qkv_kernel<<<dim3(32, 16), 512, smemA>>>(x, Wqkv);
    attn_kernel<<<BB * NWIN, 1024, smemB>>>(topk);
    proj_kernel<<<dim3(32, 16), 512, smemC>>>(Wproj, bproj, out);
}